// round 6
// baseline (speedup 1.0000x reference)
#include <cuda_runtime.h>
#include <math.h>

// feat: [B=4, C=256, H=50, W=50] f32;  rois: [R,5] f32;  out: [R,256,7,7] f32
#define CC 256
#define HW 2500
#define HH 50
#define WW 50
#define PP 7
#define NBIN 49
#define SPATIAL_SCALE 0.0625f
#define G 8                 // channels per block
#define NT 256              // threads per block
// ROI region is provably <= 18x18 cells (wh<=256px * 0.0625 -> <=17 extent, +1 ulp slack)
#define RDIM 18
#define RSTRIDE 19          // padded row stride (bank-conflict relief)
#define SLAB (RSTRIDE * RDIM)   // 342 floats per channel slab

__global__ void __launch_bounds__(NT)
roipool_kernel(const float* __restrict__ feat,
               const float* __restrict__ rois,
               float* __restrict__ out) {
    __shared__ int s_ws[PP], s_we[PP], s_hs[PP], s_he[PP];
    __shared__ int s_base;
    __shared__ float s_tile[G * SLAB];

    const int r  = blockIdx.x;          // roi
    const int cg = blockIdx.y;          // channel group (G channels)
    const int t  = threadIdx.x;

    if (t < PP) {
        const float* rp = rois + (size_t)r * 5;
        // jnp.round == round-half-to-even == rintf (RN); *0.0625 exact.
        float x1 = rintf(rp[1] * SPATIAL_SCALE);
        float y1 = rintf(rp[2] * SPATIAL_SCALE);
        float x2 = rintf(rp[3] * SPATIAL_SCALE);
        float y2 = rintf(rp[4] * SPATIAL_SCALE);
        // XLA folds x/7 into x * RN(1/7); replicate exactly.
        const float INV7 = 1.0f / 7.0f;
        float bw = __fmul_rn(fmaxf(x2 - x1 + 1.0f, 1.0f), INV7);
        float bh = __fmul_rn(fmaxf(y2 - y1 + 1.0f, 1.0f), INV7);
        float fp = (float)t;
        s_ws[t] = (int)fminf(fmaxf(floorf(__fmul_rn(bw, fp))        + x1, 0.0f), (float)WW);
        s_we[t] = (int)fminf(fmaxf(ceilf (__fmul_rn(bw, fp + 1.0f)) + x1, 0.0f), (float)WW);
        s_hs[t] = (int)fminf(fmaxf(floorf(__fmul_rn(bh, fp))        + y1, 0.0f), (float)HH);
        s_he[t] = (int)fminf(fmaxf(ceilf (__fmul_rn(bh, fp + 1.0f)) + y1, 0.0f), (float)HH);
        if (t == 0) s_base = (int)rp[0] * (CC * HW);
    }
    __syncthreads();

    // Region covering all 49 bins (bounds monotone in p).
    const int h0 = s_hs[0], w0 = s_ws[0];
    int rh = s_he[PP - 1] - h0;     // 1..18
    int rw = s_we[PP - 1] - w0;     // 1..18
    rh = min(rh, RDIM);
    rw = min(rw, RDIM);

    // Cooperative coalesced load of G channel slabs into smem.
    const int c0 = cg * G;
    const float* fb = feat + s_base + (size_t)c0 * HW + h0 * WW + w0;
    const int nelem = rh * rw;
    for (int i = t; i < G * nelem; i += NT) {
        int cl  = i / nelem;
        int rem = i - cl * nelem;
        int hh  = rem / rw;
        int ww  = rem - hh * rw;
        s_tile[cl * SLAB + hh * RSTRIDE + ww] =
            __ldg(fb + (size_t)cl * HW + hh * WW + ww);
    }
    __syncthreads();

    // 392 outputs: o = c_local*49 + p, matching out layout exactly (coalesced).
    float* ob = out + ((size_t)r * CC + c0) * NBIN;
    for (int o = t; o < G * NBIN; o += NT) {
        int cl = o / NBIN;
        int p  = o - cl * NBIN;
        int pw = p % PP;
        int ph = p / PP;

        int ws = s_ws[pw] - w0, nw = s_we[pw] - s_ws[pw];
        int hs = s_hs[ph] - h0, nh = s_he[ph] - s_hs[ph];

        const float* tp = s_tile + cl * SLAB;
        // Bin window provably <= 4x4: fixed predicated gather from smem.
        float m = -INFINITY;
        #pragma unroll
        for (int i = 0; i < 4; ++i) {
            int hh = min(hs + i, RDIM - 1);
            #pragma unroll
            for (int j = 0; j < 4; ++j) {
                int ww = min(ws + j, RDIM);   // RSTRIDE-1 = 18 max index, in-slab
                float v = tp[hh * RSTRIDE + ww];
                m = fmaxf(m, ((i < nh) && (j < nw)) ? v : -INFINITY);
            }
        }
        ob[o] = (m == -INFINITY) ? 0.0f : m;
    }
}

extern "C" void kernel_launch(void* const* d_in, const int* in_sizes, int n_in,
                              void* d_out, int out_size) {
    const float* feat = (const float*)d_in[0];
    const float* rois = (const float*)d_in[1];
    float* out = (float*)d_out;

    int R = in_sizes[1] / 5;            // 128
    dim3 grid(R, CC / G);               // 128 x 32 = 4096 blocks
    roipool_kernel<<<grid, NT>>>(feat, rois, out);
}

// round 7
// speedup vs baseline: 1.3243x; 1.3243x over previous
#include <cuda_runtime.h>
#include <math.h>

// feat: [B=4, C=256, H=50, W=50] f32;  rois: [R,5] f32;  out: [R,256,7,7] f32
#define BB 4
#define CC 256
#define HH 50
#define WW 50
#define HW 2500
#define PP 7
#define NBIN 49
#define SPATIAL_SCALE 0.0625f

// Transposed features: [b][hw][c] — gathers become coalesced along c.
__device__ float g_featT[BB * HW * CC];

__global__ void __launch_bounds__(256)
transpose_kernel(const float* __restrict__ feat) {
    __shared__ float tile[32][33];
    const int b  = blockIdx.z;
    const int c0 = blockIdx.y * 32;
    const int s0 = blockIdx.x * 32;          // hw tile origin
    const int tx = threadIdx.x;              // 0..31
    const int ty = threadIdx.y;              // 0..7

    #pragma unroll
    for (int j = 0; j < 32; j += 8) {
        int s = s0 + tx;
        if (s < HW)
            tile[ty + j][tx] = feat[((size_t)b * CC + (c0 + ty + j)) * HW + s];
    }
    __syncthreads();
    #pragma unroll
    for (int j = 0; j < 32; j += 8) {
        int s = s0 + ty + j;
        if (s < HW)
            g_featT[((size_t)b * HW + s) * CC + (c0 + tx)] = tile[tx][ty + j];
    }
}

__global__ void __launch_bounds__(256)
roipool_kernel(const float* __restrict__ rois, float* __restrict__ out) {
    __shared__ int   s_bnd[NBIN];            // ws | we<<8 | hs<<16 | he<<24
    __shared__ int   s_base;                 // b * HW * CC
    __shared__ float s_out[NBIN][33];        // [bin][channel], padded

    const int r    = blockIdx.x;             // roi
    const int cg   = blockIdx.y;             // channel group (32 ch)
    const int t    = threadIdx.x;
    const int lane = t & 31;
    const int wid  = t >> 5;                  // 8 warps

    if (t < NBIN) {
        const float* rp = rois + (size_t)r * 5;
        // jnp.round == round-half-to-even == rintf (RN); *0.0625 exact.
        float x1 = rintf(rp[1] * SPATIAL_SCALE);
        float y1 = rintf(rp[2] * SPATIAL_SCALE);
        float x2 = rintf(rp[3] * SPATIAL_SCALE);
        float y2 = rintf(rp[4] * SPATIAL_SCALE);
        // XLA folds x/7 into x * RN(1/7); replicate exactly.
        const float INV7 = 1.0f / 7.0f;
        float bw = __fmul_rn(fmaxf(x2 - x1 + 1.0f, 1.0f), INV7);
        float bh = __fmul_rn(fmaxf(y2 - y1 + 1.0f, 1.0f), INV7);
        float fpw = (float)(t % PP);
        float fph = (float)(t / PP);
        int ws = (int)fminf(fmaxf(floorf(__fmul_rn(bw, fpw))        + x1, 0.0f), (float)WW);
        int we = (int)fminf(fmaxf(ceilf (__fmul_rn(bw, fpw + 1.0f)) + x1, 0.0f), (float)WW);
        int hs = (int)fminf(fmaxf(floorf(__fmul_rn(bh, fph))        + y1, 0.0f), (float)HH);
        int he = (int)fminf(fmaxf(ceilf (__fmul_rn(bh, fph + 1.0f)) + y1, 0.0f), (float)HH);
        s_bnd[t] = ws | (we << 8) | (hs << 16) | (he << 24);
        if (t == 0) s_base = (int)rp[0] * (HW * CC);
    }
    __syncthreads();

    const float* fb = g_featT + s_base + cg * 32 + lane;

    // Warp `wid` handles bins p = wid, wid+8, ... All lanes share bounds:
    // zero divergence, every load is one coalesced 128B wavefront.
    for (int p = wid; p < NBIN; p += 8) {
        int bnd = s_bnd[p];
        int ws =  bnd        & 0xFF;
        int we = (bnd >> 8)  & 0xFF;
        int hs = (bnd >> 16) & 0xFF;
        int he = (bnd >> 24) & 0xFF;

        float m = -INFINITY;
        for (int h = hs; h < he; ++h) {
            const float* q = fb + (h * WW + ws) * CC;
            #pragma unroll 2
            for (int w = ws; w < we; ++w) {
                m = fmaxf(m, __ldg(q));
                q += CC;
            }
        }
        s_out[p][lane] = (m == -INFINITY) ? 0.0f : m;   // empty bin -> 0
    }
    __syncthreads();

    // Coalesced-ish writeback: out[r][c0+c][p], p fastest.
    float* ob = out + ((size_t)r * CC + cg * 32) * NBIN;
    const int c  = t >> 3;      // 0..31
    const int p0 = t & 7;
    #pragma unroll
    for (int p = p0; p < NBIN; p += 8)
        ob[c * NBIN + p] = s_out[p][c];
}

extern "C" void kernel_launch(void* const* d_in, const int* in_sizes, int n_in,
                              void* d_out, int out_size) {
    const float* feat = (const float*)d_in[0];
    const float* rois = (const float*)d_in[1];
    float* out = (float*)d_out;

    int R = in_sizes[1] / 5;   // 128

    dim3 tgrid((HW + 31) / 32, CC / 32, BB);   // 79 x 8 x 4
    dim3 tblk(32, 8);
    transpose_kernel<<<tgrid, tblk>>>(feat);

    dim3 ggrid(R, CC / 32);                    // 128 x 8
    roipool_kernel<<<ggrid, 256>>>(rois, out);
}